// round 8
// baseline (speedup 1.0000x reference)
#include <cuda_runtime.h>
#include <cuda_bf16.h>
#include <math.h>

// ---------------------------------------------------------------------------
// VQ-VAE forward on GB300 (sm_103a). Round 8: packed f32x2 FFMA (FFMA2).
//   - SGEMM + VQ cross-loop use fma.rn.f32x2: per-scalar k-ascending chains
//     are BITWISE IDENTICAL to round 7 (argmin-safe), at 2x fma-pipe rate.
//   - GEMM3 remains eliminated via P-table (h3 = relu(b3 + sum_n P[n,idx,:])).
// Output layout: recon | z_e | emb  (fp32, concatenated)
// ---------------------------------------------------------------------------

#define Bsz    32768
#define IN_DIM 784
#define H0     512
#define H1     1024
#define Kc     128
#define Dd     128
#define Nn     8

// Scratch (__device__ globals; no allocation allowed)
__device__ __align__(16) float g_h1[Bsz * H0];            // 64 MB
__device__ __align__(16) float g_h3[Bsz * H0];            // 64 MB
__device__ __align__(16) float g_P[Nn * Kc * H0];         // 2 MB
__device__ int   g_idx[Bsz * Nn];                         // 1 MB

// ---- packed f32x2 helpers -------------------------------------------------
typedef unsigned long long u64t;

__device__ __forceinline__ void ffma2(u64t& d, u64t a, u64t b) {
    asm("fma.rn.f32x2 %0, %1, %2, %0;" : "+l"(d) : "l"(a), "l"(b));
}
__device__ __forceinline__ u64t pack2(float lo, float hi) {
    u64t r;
    asm("mov.b64 %0, {%1, %2};" : "=l"(r) : "f"(lo), "f"(hi));
    return r;
}
__device__ __forceinline__ void unpack2(u64t v, float& lo, float& hi) {
    asm("mov.b64 {%0, %1}, %2;" : "=f"(lo), "=f"(hi) : "l"(v));
}

// ---------------------------------------------------------------------------
// Tiled SGEMM with FFMA2: C[M,N] = act(A[M,K] @ W[K,N] + bias)
// BM=BN=128, BK=8, 256 threads, 8x8 microtile (as 8x4 f32x2 pairs),
// double-buffered smem. A staged DUPLICATED as (a,a) 64-bit words; B pairs
// are adjacent columns read directly as packed 64-bit. Per-scalar accumulation
// remains strict k-ascending rn-FMA (bitwise == scalar version; argmin-safe).
// ACT: 0=none, 1=relu, 2=tanh
// ---------------------------------------------------------------------------
template <int ACT>
__global__ __launch_bounds__(256, 2)
void gemm_kernel(const float* __restrict__ A, const float* __restrict__ W,
                 const float* __restrict__ bias, float* __restrict__ C,
                 int M, int N, int K)
{
    __shared__ u64t  As2[2][8][128];   // duplicated (a,a) pairs, 16 KB
    __shared__ float Bs[2][8][128];    // 8 KB

    const int tid = threadIdx.x;
    const int m0  = blockIdx.y * 128;
    const int n0  = blockIdx.x * 128;

    const int tx = tid & 15;
    const int ty = tid >> 4;
    const int row0 = ty * 8;
    const int col0 = tx * 8;

    const int a_r = tid >> 1;
    const int a_q = (tid & 1) * 4;
    const int b_r = tid >> 5;
    const int b_q = (tid & 31) * 4;

    const bool b_ok = (n0 + b_q < N);

    u64t acc2[8][4];
#pragma unroll
    for (int i = 0; i < 8; ++i)
#pragma unroll
        for (int j = 0; j < 4; ++j) acc2[i][j] = 0ULL;

    const int nsteps = K >> 3;

    // prologue: stage k-step 0 into buffer 0
    float4 av = *reinterpret_cast<const float4*>(&A[(size_t)(m0 + a_r) * K + a_q]);
    float4 bv = make_float4(0.f, 0.f, 0.f, 0.f);
    if (b_ok)
        bv = *reinterpret_cast<const float4*>(&W[(size_t)b_r * N + n0 + b_q]);
    As2[0][a_q + 0][a_r] = pack2(av.x, av.x);
    As2[0][a_q + 1][a_r] = pack2(av.y, av.y);
    As2[0][a_q + 2][a_r] = pack2(av.z, av.z);
    As2[0][a_q + 3][a_r] = pack2(av.w, av.w);
    *reinterpret_cast<float4*>(&Bs[0][b_r][b_q]) = bv;
    __syncthreads();

    for (int s = 0; s < nsteps; ++s) {
        const int cur = s & 1;
        const bool more = (s + 1 < nsteps);

        if (more) {
            const int k0 = (s + 1) << 3;
            av = *reinterpret_cast<const float4*>(
                &A[(size_t)(m0 + a_r) * K + k0 + a_q]);
            if (b_ok)
                bv = *reinterpret_cast<const float4*>(
                    &W[(size_t)(k0 + b_r) * N + n0 + b_q]);
        }

#pragma unroll
        for (int kk = 0; kk < 8; ++kk) {
            u64t a2[8];
#pragma unroll
            for (int i = 0; i < 8; ++i)
                a2[i] = As2[cur][kk][row0 + i];
            const ulonglong2 bl = *reinterpret_cast<const ulonglong2*>(&Bs[cur][kk][col0]);
            const ulonglong2 bh = *reinterpret_cast<const ulonglong2*>(&Bs[cur][kk][col0 + 4]);
#pragma unroll
            for (int i = 0; i < 8; ++i) {
                ffma2(acc2[i][0], a2[i], bl.x);
                ffma2(acc2[i][1], a2[i], bl.y);
                ffma2(acc2[i][2], a2[i], bh.x);
                ffma2(acc2[i][3], a2[i], bh.y);
            }
        }

        if (more) {
            const int nxt = cur ^ 1;
            As2[nxt][a_q + 0][a_r] = pack2(av.x, av.x);
            As2[nxt][a_q + 1][a_r] = pack2(av.y, av.y);
            As2[nxt][a_q + 2][a_r] = pack2(av.z, av.z);
            As2[nxt][a_q + 3][a_r] = pack2(av.w, av.w);
            *reinterpret_cast<float4*>(&Bs[nxt][b_r][b_q]) = bv;
        }
        __syncthreads();
    }

#pragma unroll
    for (int i = 0; i < 8; ++i) {
        const size_t rowoff = (size_t)(m0 + row0 + i) * N;
#pragma unroll
        for (int j = 0; j < 4; ++j) {
            float c0, c1;
            unpack2(acc2[i][j], c0, c1);
            const int n_a = n0 + col0 + 2 * j;
            const int n_b = n_a + 1;
            if (n_a < N) {
                float c = c0;
                if (bias) c = __fadd_rn(c, bias[n_a]);
                if (ACT == 1) c = fmaxf(c, 0.0f);
                if (ACT == 2) c = tanhf(c);
                C[rowoff + n_a] = c;
            }
            if (n_b < N) {
                float c = c1;
                if (bias) c = __fadd_rn(c, bias[n_b]);
                if (ACT == 1) c = fmaxf(c, 0.0f);
                if (ACT == 2) c = tanhf(c);
                C[rowoff + n_b] = c;
            }
        }
    }
}

// ---------------------------------------------------------------------------
// Fused VQ (jax-rounding-replicated; see R3). Cross-loop uses FFMA2 with
// per-scalar chains bitwise identical to the scalar version.
// ---------------------------------------------------------------------------
#define VQ_SAMPLES 8
#define VQ_SMEM ((Kc * Dd + VQ_SAMPLES * H1 + Kc) * (int)sizeof(float))

__global__ __launch_bounds__(256, 2)
void vq_kernel(const float* __restrict__ z_e, const float* __restrict__ E,
               float* __restrict__ emb, int* __restrict__ idx_out)
{
    extern __shared__ float sh[];
    float* E_sh  = sh;                       // [Dd][Kc]
    float* z_sh  = sh + Kc * Dd;             // [8][1024]
    float* e2_sh = z_sh + VQ_SAMPLES * H1;   // [Kc]

    const int tid  = threadIdx.x;
    const int warp = tid >> 5;
    const int lane = tid & 31;
    const size_t b0 = (size_t)blockIdx.x * VQ_SAMPLES;

#pragma unroll
    for (int i = 0; i < (Kc * Dd / 4) / 256; ++i)
        reinterpret_cast<float4*>(E_sh)[tid + i * 256] =
            reinterpret_cast<const float4*>(E)[tid + i * 256];
#pragma unroll
    for (int i = 0; i < (VQ_SAMPLES * H1 / 4) / 256; ++i)
        reinterpret_cast<float4*>(z_sh)[tid + i * 256] =
            reinterpret_cast<const float4*>(z_e + b0 * H1)[tid + i * 256];
    __syncthreads();

    // e2[k]: d-ascending, separate mul/add (matches XLA reduce emitter)
    if (tid < Kc) {
        float s = 0.f;
#pragma unroll 16
        for (int d = 0; d < Dd; ++d) {
            float v = E_sh[d * Kc + tid];
            s = __fadd_rn(s, __fmul_rn(v, v));
        }
        e2_sh[tid] = s;
    }
    __syncthreads();

    const int s = warp;
    const float* zrow = z_sh + s * H1;

    // z2[n]: d-ascending, separate mul/add
    float s2 = 0.f;
    {
        const int n = lane & 7;
#pragma unroll 16
        for (int d = 0; d < Dd; ++d) {
            float v = zrow[d * 8 + n];
            s2 = __fadd_rn(s2, __fmul_rn(v, v));
        }
    }
    float z2v[Nn];
#pragma unroll
    for (int n = 0; n < Nn; ++n)
        z2v[n] = __shfl_sync(0xFFFFFFFFu, s2, n);

    // cross: d-ascending chains, packed 2 codes per FFMA2
    u64t acc2[Nn][2];
#pragma unroll
    for (int n = 0; n < Nn; ++n) {
        acc2[n][0] = 0ULL;
        acc2[n][1] = 0ULL;
    }

#pragma unroll 4
    for (int d = 0; d < Dd; ++d) {
        const ulonglong2 ev = *reinterpret_cast<const ulonglong2*>(&E_sh[d * Kc + lane * 4]);
        const float4 za = *reinterpret_cast<const float4*>(&zrow[d * 8]);
        const float4 zb = *reinterpret_cast<const float4*>(&zrow[d * 8 + 4]);
        u64t z0 = pack2(za.x, za.x), z1 = pack2(za.y, za.y);
        u64t z2p = pack2(za.z, za.z), z3 = pack2(za.w, za.w);
        u64t z4 = pack2(zb.x, zb.x), z5 = pack2(zb.y, zb.y);
        u64t z6 = pack2(zb.z, zb.z), z7 = pack2(zb.w, zb.w);
        ffma2(acc2[0][0], z0, ev.x); ffma2(acc2[0][1], z0, ev.y);
        ffma2(acc2[1][0], z1, ev.x); ffma2(acc2[1][1], z1, ev.y);
        ffma2(acc2[2][0], z2p, ev.x); ffma2(acc2[2][1], z2p, ev.y);
        ffma2(acc2[3][0], z3, ev.x); ffma2(acc2[3][1], z3, ev.y);
        ffma2(acc2[4][0], z4, ev.x); ffma2(acc2[4][1], z4, ev.y);
        ffma2(acc2[5][0], z5, ev.x); ffma2(acc2[5][1], z5, ev.y);
        ffma2(acc2[6][0], z6, ev.x); ffma2(acc2[6][1], z6, ev.y);
        ffma2(acc2[7][0], z7, ev.x); ffma2(acc2[7][1], z7, ev.y);
    }

    const float4 e4 = *reinterpret_cast<const float4*>(&e2_sh[lane * 4]);

    int bi_arr[Nn];
#pragma unroll
    for (int n = 0; n < Nn; ++n) {
        const float z2n = z2v[n];
        float c0, c1, c2, c3;
        unpack2(acc2[n][0], c0, c1);
        unpack2(acc2[n][1], c2, c3);
        float v0 = __fadd_rn(fmaf(-2.0f, c0, z2n), e4.x);
        float v1 = __fadd_rn(fmaf(-2.0f, c1, z2n), e4.y);
        float v2 = __fadd_rn(fmaf(-2.0f, c2, z2n), e4.z);
        float v3 = __fadd_rn(fmaf(-2.0f, c3, z2n), e4.w);

        float best = v0; int bi = lane * 4;
        if (v1 < best) { best = v1; bi = lane * 4 + 1; }
        if (v2 < best) { best = v2; bi = lane * 4 + 2; }
        if (v3 < best) { best = v3; bi = lane * 4 + 3; }
#pragma unroll
        for (int off = 16; off > 0; off >>= 1) {
            float ov = __shfl_xor_sync(0xFFFFFFFFu, best, off);
            int   oi = __shfl_xor_sync(0xFFFFFFFFu, bi,  off);
            if (ov < best || (ov == best && oi < bi)) { best = ov; bi = oi; }
        }
        bi_arr[n] = bi;
    }

    int bsel = bi_arr[0];
#pragma unroll
    for (int n = 1; n < Nn; ++n)
        if ((lane & 7) == n) bsel = bi_arr[n];

    if (lane < Nn)
        idx_out[(b0 + s) * Nn + lane] = bsel;

    float* erow = emb + (b0 + s) * H1;
#pragma unroll
    for (int t = 0; t < H1 / 32; ++t) {
        int i = t * 32 + lane;
        erow[i] = E_sh[(i >> 3) * Kc + bsel];
    }
}

// ---------------------------------------------------------------------------
// P[n,k,j] = sum_d E[d,k] * W3[d*8+n, j]
// ---------------------------------------------------------------------------
__global__ __launch_bounds__(128)
void build_P(const float* __restrict__ E, const float* __restrict__ W3,
             float* __restrict__ P)
{
    const int n = blockIdx.x >> 7;
    const int k = blockIdx.x & 127;
    const int j = threadIdx.x * 4;

    float4 acc = make_float4(0.f, 0.f, 0.f, 0.f);
#pragma unroll 8
    for (int d = 0; d < Dd; ++d) {
        const float e = __ldg(&E[d * Kc + k]);
        const float4 w = *reinterpret_cast<const float4*>(
            &W3[(size_t)(d * 8 + n) * H0 + j]);
        acc.x = fmaf(e, w.x, acc.x);
        acc.y = fmaf(e, w.y, acc.y);
        acc.z = fmaf(e, w.z, acc.z);
        acc.w = fmaf(e, w.w, acc.w);
    }
    *reinterpret_cast<float4*>(&P[((size_t)n * Kc + k) * H0 + j]) = acc;
}

// ---------------------------------------------------------------------------
// h3[b,j] = relu(b3[j] + sum_n P[n, idx[b,n], j])
// ---------------------------------------------------------------------------
__global__ __launch_bounds__(128, 8)
void decode_h3(const float* __restrict__ P, const int* __restrict__ idx,
               const float* __restrict__ b3, float* __restrict__ h3)
{
    __shared__ int sid[Nn];
    const int b = blockIdx.x;
    const int tid = threadIdx.x;
    if (tid < Nn) sid[tid] = idx[b * Nn + tid];
    __syncthreads();

    const int j = tid * 4;
    float4 acc = *reinterpret_cast<const float4*>(&b3[j]);
#pragma unroll
    for (int n = 0; n < Nn; ++n) {
        const float4 p = *reinterpret_cast<const float4*>(
            &P[((size_t)n * Kc + sid[n]) * H0 + j]);
        acc.x = __fadd_rn(acc.x, p.x);
        acc.y = __fadd_rn(acc.y, p.y);
        acc.z = __fadd_rn(acc.z, p.z);
        acc.w = __fadd_rn(acc.w, p.w);
    }
    acc.x = fmaxf(acc.x, 0.f);
    acc.y = fmaxf(acc.y, 0.f);
    acc.z = fmaxf(acc.z, 0.f);
    acc.w = fmaxf(acc.w, 0.f);
    *reinterpret_cast<float4*>(&h3[(size_t)b * H0 + j]) = acc;
}

// ---------------------------------------------------------------------------
extern "C" void kernel_launch(void* const* d_in, const int* in_sizes, int n_in,
                              void* d_out, int out_size)
{
    const float* x  = (const float*)d_in[0];
    const float* W1 = (const float*)d_in[1];
    const float* b1 = (const float*)d_in[2];
    const float* W2 = (const float*)d_in[3];
    const float* b2 = (const float*)d_in[4];
    const float* W3 = (const float*)d_in[5];
    const float* b3 = (const float*)d_in[6];
    const float* W4 = (const float*)d_in[7];
    const float* b4 = (const float*)d_in[8];
    const float* E  = (const float*)d_in[9];

    float* out   = (float*)d_out;
    float* recon = out;
    float* z_e   = out + (size_t)Bsz * IN_DIM;
    float* emb   = out + (size_t)Bsz * (IN_DIM + H1);

    void *p_h1, *p_h3, *p_P, *p_idx;
    cudaGetSymbolAddress(&p_h1,  g_h1);
    cudaGetSymbolAddress(&p_h3,  g_h3);
    cudaGetSymbolAddress(&p_P,   g_P);
    cudaGetSymbolAddress(&p_idx, g_idx);
    float* h1f = (float*)p_h1;
    float* h3f = (float*)p_h3;
    float* Pf  = (float*)p_P;
    int*   idxf = (int*)p_idx;

    static bool attr_set = false;
    if (!attr_set) {
        cudaFuncSetAttribute(vq_kernel,
                             cudaFuncAttributeMaxDynamicSharedMemorySize, VQ_SMEM);
        attr_set = true;
    }

    // P table (independent of batch chain; tiny)
    build_P<<<Nn * Kc, 128>>>(E, W3, Pf);

    // GEMM1: h1 = relu(x @ W1 + b1)
    {
        dim3 grid(H0 / 128, Bsz / 128);
        gemm_kernel<1><<<grid, 256>>>(x, W1, b1, h1f, Bsz, H0, IN_DIM);
    }
    // GEMM2: z_e = h1 @ W2 + b2
    {
        dim3 grid(H1 / 128, Bsz / 128);
        gemm_kernel<0><<<grid, 256>>>(h1f, W2, b2, z_e, Bsz, H1, H0);
    }
    // Fused VQ: z_e -> emb, idx
    vq_kernel<<<Bsz / VQ_SAMPLES, 256, VQ_SMEM>>>(z_e, E, emb, idxf);

    // h3 via P-table gather-sum (replaces GEMM3)
    decode_h3<<<Bsz, 128>>>(Pf, idxf, b3, h3f);

    // GEMM4: recon = tanh(h3 @ W4 + b4)
    {
        dim3 grid((IN_DIM + 127) / 128, Bsz / 128);
        gemm_kernel<2><<<grid, 256>>>(h3f, W4, b4, recon, Bsz, IN_DIM, H0);
    }
}

// round 10
// speedup vs baseline: 1.3183x; 1.3183x over previous
#include <cuda_runtime.h>
#include <cuda_bf16.h>
#include <math.h>

// ---------------------------------------------------------------------------
// VQ-VAE forward on GB300 (sm_103a). Round 9:
//   - GEMM1/2: R7 scalar double-buffered SGEMM (exact fp32 chain; argmin-safe)
//   - VQ fused (jax-rounding-replicated) -> emb + idx
//   - h3 via P-table gather-sum (GEMM3 eliminated)
//   - GEMM4: mma.sync m16n8k8 TF32 x3 (downstream-smooth; ~1e-6 on recon)
// Output layout: recon | z_e | emb  (fp32, concatenated)
// ---------------------------------------------------------------------------

#define Bsz    32768
#define IN_DIM 784
#define H0     512
#define H1     1024
#define Kc     128
#define Dd     128
#define Nn     8

// Scratch (__device__ globals; no allocation allowed)
__device__ __align__(16) float g_h1[Bsz * H0];            // 64 MB
__device__ __align__(16) float g_h3[Bsz * H0];            // 64 MB
__device__ __align__(16) float g_P[Nn * Kc * H0];         // 2 MB
__device__ int   g_idx[Bsz * Nn];                         // 1 MB

// ---------------------------------------------------------------------------
// Scalar tiled SGEMM (R7): C[M,N] = act(A[M,K] @ W[K,N] + bias)
// BM=BN=128, BK=8, 256 threads, 8x8 microtile, double-buffered smem.
// Strict k-ascending FFMA per output element (argmin-safe).
// ACT: 0=none, 1=relu, 2=tanh
// ---------------------------------------------------------------------------
template <int ACT>
__global__ __launch_bounds__(256, 2)
void gemm_kernel(const float* __restrict__ A, const float* __restrict__ W,
                 const float* __restrict__ bias, float* __restrict__ C,
                 int M, int N, int K)
{
    __shared__ float As[2][8][128];
    __shared__ float Bs[2][8][128];

    const int tid = threadIdx.x;
    const int m0  = blockIdx.y * 128;
    const int n0  = blockIdx.x * 128;

    const int tx = tid & 15;
    const int ty = tid >> 4;
    const int row0 = ty * 8;
    const int col0 = tx * 8;

    const int a_r = tid >> 1;
    const int a_q = (tid & 1) * 4;
    const int b_r = tid >> 5;
    const int b_q = (tid & 31) * 4;

    const bool b_ok = (n0 + b_q < N);

    float acc[8][8];
#pragma unroll
    for (int i = 0; i < 8; ++i)
#pragma unroll
        for (int j = 0; j < 8; ++j) acc[i][j] = 0.0f;

    const int nsteps = K >> 3;

    float4 av = *reinterpret_cast<const float4*>(&A[(size_t)(m0 + a_r) * K + a_q]);
    float4 bv = make_float4(0.f, 0.f, 0.f, 0.f);
    if (b_ok)
        bv = *reinterpret_cast<const float4*>(&W[(size_t)b_r * N + n0 + b_q]);
    As[0][a_q + 0][a_r] = av.x;
    As[0][a_q + 1][a_r] = av.y;
    As[0][a_q + 2][a_r] = av.z;
    As[0][a_q + 3][a_r] = av.w;
    *reinterpret_cast<float4*>(&Bs[0][b_r][b_q]) = bv;
    __syncthreads();

    for (int s = 0; s < nsteps; ++s) {
        const int cur = s & 1;
        const bool more = (s + 1 < nsteps);

        if (more) {
            const int k0 = (s + 1) << 3;
            av = *reinterpret_cast<const float4*>(
                &A[(size_t)(m0 + a_r) * K + k0 + a_q]);
            if (b_ok)
                bv = *reinterpret_cast<const float4*>(
                    &W[(size_t)(k0 + b_r) * N + n0 + b_q]);
        }

#pragma unroll
        for (int kk = 0; kk < 8; ++kk) {
            float a[8], b[8];
            *reinterpret_cast<float4*>(&a[0]) = *reinterpret_cast<const float4*>(&As[cur][kk][row0]);
            *reinterpret_cast<float4*>(&a[4]) = *reinterpret_cast<const float4*>(&As[cur][kk][row0 + 4]);
            *reinterpret_cast<float4*>(&b[0]) = *reinterpret_cast<const float4*>(&Bs[cur][kk][col0]);
            *reinterpret_cast<float4*>(&b[4]) = *reinterpret_cast<const float4*>(&Bs[cur][kk][col0 + 4]);
#pragma unroll
            for (int i = 0; i < 8; ++i)
#pragma unroll
                for (int j = 0; j < 8; ++j)
                    acc[i][j] = fmaf(a[i], b[j], acc[i][j]);
        }

        if (more) {
            const int nxt = cur ^ 1;
            As[nxt][a_q + 0][a_r] = av.x;
            As[nxt][a_q + 1][a_r] = av.y;
            As[nxt][a_q + 2][a_r] = av.z;
            As[nxt][a_q + 3][a_r] = av.w;
            *reinterpret_cast<float4*>(&Bs[nxt][b_r][b_q]) = bv;
        }
        __syncthreads();
    }

#pragma unroll
    for (int i = 0; i < 8; ++i) {
        const size_t rowoff = (size_t)(m0 + row0 + i) * N;
#pragma unroll
        for (int j = 0; j < 8; ++j) {
            const int n = n0 + col0 + j;
            if (n < N) {
                float c = acc[i][j];
                if (bias) c = __fadd_rn(c, bias[n]);
                if (ACT == 1) c = fmaxf(c, 0.0f);
                if (ACT == 2) c = tanhf(c);
                C[rowoff + n] = c;
            }
        }
    }
}

// ---------------------------------------------------------------------------
// GEMM4 via tensor cores: recon = tanh(h3 @ W4 + b4), 3xTF32.
// M=32768, N=784, K=512. Block tile 128x64xBK16, 256 thr = 8 warps (4m x 2n),
// warp tile 32x32 = 2 m-subtiles(16) x 4 n-subtiles(8). Padded smem
// (A:[128][20], B:[16][72]) -> conflict-free fragment LDS.
// ---------------------------------------------------------------------------
__device__ __forceinline__ void split_tf32(float a, unsigned& hi, unsigned& lo) {
    unsigned h;
    asm("cvt.rna.tf32.f32 %0, %1;" : "=r"(h) : "f"(a));
    float l = a - __uint_as_float(h);
    unsigned lr;
    asm("cvt.rna.tf32.f32 %0, %1;" : "=r"(lr) : "f"(l));
    hi = h; lo = lr;
}

__device__ __forceinline__ void mma_tf32(float4& d, const unsigned* a, const unsigned* b) {
    asm("mma.sync.aligned.m16n8k8.row.col.f32.tf32.tf32.f32 "
        "{%0,%1,%2,%3}, {%4,%5,%6,%7}, {%8,%9}, {%0,%1,%2,%3};"
        : "+f"(d.x), "+f"(d.y), "+f"(d.z), "+f"(d.w)
        : "r"(a[0]), "r"(a[1]), "r"(a[2]), "r"(a[3]), "r"(b[0]), "r"(b[1]));
}

__global__ __launch_bounds__(256, 2)
void gemm4_tc(const float* __restrict__ A, const float* __restrict__ W,
              const float* __restrict__ bias, float* __restrict__ C)
{
    const int M = Bsz, N = IN_DIM, K = H0;   // 32768, 784, 512
    __shared__ float As[2][128][20];         // padded (conflict-free frags)
    __shared__ float Bs[2][16][72];

    const int tid  = threadIdx.x;
    const int warp = tid >> 5;
    const int lane = tid & 31;
    const int gid  = lane >> 2;              // 0..7
    const int tig  = lane & 3;               // 0..3

    const int m0 = blockIdx.y * 128;
    const int n0 = blockIdx.x * 64;

    const int wm = (warp >> 1) * 32;         // warp m-offset (0..96)
    const int wn = (warp & 1) * 32;          // warp n-offset (0 or 32)

    // gmem load mapping
    const int a_row = tid >> 2;              // 0..63 (plus +64 for second half)
    const int a_q   = (tid & 3) * 4;         // 0,4,8,12
    const int b_row = tid >> 4;              // 0..15
    const int b_q   = (tid & 15) * 4;        // 0..60
    const bool b_ok = (n0 + b_q < N);

    float4 acc[2][4];
#pragma unroll
    for (int mt = 0; mt < 2; ++mt)
#pragma unroll
        for (int nt = 0; nt < 4; ++nt)
            acc[mt][nt] = make_float4(0.f, 0.f, 0.f, 0.f);

    const int nsteps = K / 16;               // 32

    // prologue
    float4 av0 = *reinterpret_cast<const float4*>(&A[(size_t)(m0 + a_row) * K + a_q]);
    float4 av1 = *reinterpret_cast<const float4*>(&A[(size_t)(m0 + 64 + a_row) * K + a_q]);
    float4 bv  = make_float4(0.f, 0.f, 0.f, 0.f);
    if (b_ok)
        bv = *reinterpret_cast<const float4*>(&W[(size_t)b_row * N + n0 + b_q]);
    *reinterpret_cast<float4*>(&As[0][a_row][a_q])      = av0;
    *reinterpret_cast<float4*>(&As[0][64 + a_row][a_q]) = av1;
    *reinterpret_cast<float4*>(&Bs[0][b_row][b_q])      = bv;
    __syncthreads();

    for (int s = 0; s < nsteps; ++s) {
        const int cur = s & 1;
        const bool more = (s + 1 < nsteps);

        if (more) {
            const int k0 = (s + 1) * 16;
            av0 = *reinterpret_cast<const float4*>(&A[(size_t)(m0 + a_row) * K + k0 + a_q]);
            av1 = *reinterpret_cast<const float4*>(&A[(size_t)(m0 + 64 + a_row) * K + k0 + a_q]);
            if (b_ok)
                bv = *reinterpret_cast<const float4*>(&W[(size_t)(k0 + b_row) * N + n0 + b_q]);
        }

#pragma unroll
        for (int k8 = 0; k8 < 16; k8 += 8) {
            unsigned ahi[2][4], alo[2][4];
#pragma unroll
            for (int mt = 0; mt < 2; ++mt) {
                const int rb = wm + mt * 16;
                float af0 = As[cur][rb + gid][k8 + tig];
                float af1 = As[cur][rb + gid + 8][k8 + tig];
                float af2 = As[cur][rb + gid][k8 + tig + 4];
                float af3 = As[cur][rb + gid + 8][k8 + tig + 4];
                split_tf32(af0, ahi[mt][0], alo[mt][0]);
                split_tf32(af1, ahi[mt][1], alo[mt][1]);
                split_tf32(af2, ahi[mt][2], alo[mt][2]);
                split_tf32(af3, ahi[mt][3], alo[mt][3]);
            }
            unsigned bhi[4][2], blo[4][2];
#pragma unroll
            for (int nt = 0; nt < 4; ++nt) {
                const int cb = wn + nt * 8 + gid;
                float bf0 = Bs[cur][k8 + tig][cb];
                float bf1 = Bs[cur][k8 + tig + 4][cb];
                split_tf32(bf0, bhi[nt][0], blo[nt][0]);
                split_tf32(bf1, bhi[nt][1], blo[nt][1]);
            }
#pragma unroll
            for (int mt = 0; mt < 2; ++mt)
#pragma unroll
                for (int nt = 0; nt < 4; ++nt) {
                    mma_tf32(acc[mt][nt], alo[mt], bhi[nt]);
                    mma_tf32(acc[mt][nt], ahi[mt], blo[nt]);
                    mma_tf32(acc[mt][nt], ahi[mt], bhi[nt]);
                }
        }

        if (more) {
            const int nxt = cur ^ 1;
            *reinterpret_cast<float4*>(&As[nxt][a_row][a_q])      = av0;
            *reinterpret_cast<float4*>(&As[nxt][64 + a_row][a_q]) = av1;
            *reinterpret_cast<float4*>(&Bs[nxt][b_row][b_q])      = bv;
        }
        __syncthreads();
    }

    // epilogue: bias + tanh
#pragma unroll
    for (int mt = 0; mt < 2; ++mt) {
        const int r0 = m0 + wm + mt * 16 + gid;
        const int r1 = r0 + 8;
#pragma unroll
        for (int nt = 0; nt < 4; ++nt) {
            const int c0 = n0 + wn + nt * 8 + 2 * tig;
            const int c1 = c0 + 1;
            if (c0 < N) {
                const float bb = bias[c0];
                C[(size_t)r0 * N + c0] = tanhf(__fadd_rn(acc[mt][nt].x, bb));
                C[(size_t)r1 * N + c0] = tanhf(__fadd_rn(acc[mt][nt].z, bb));
            }
            if (c1 < N) {
                const float bb = bias[c1];
                C[(size_t)r0 * N + c1] = tanhf(__fadd_rn(acc[mt][nt].y, bb));
                C[(size_t)r1 * N + c1] = tanhf(__fadd_rn(acc[mt][nt].w, bb));
            }
        }
    }
}

// ---------------------------------------------------------------------------
// Fused VQ (jax-rounding-replicated; see R3). Scalar FFMA chains.
// ---------------------------------------------------------------------------
#define VQ_SAMPLES 8
#define VQ_SMEM ((Kc * Dd + VQ_SAMPLES * H1 + Kc) * (int)sizeof(float))

__global__ __launch_bounds__(256, 2)
void vq_kernel(const float* __restrict__ z_e, const float* __restrict__ E,
               float* __restrict__ emb, int* __restrict__ idx_out)
{
    extern __shared__ float sh[];
    float* E_sh  = sh;                       // [Dd][Kc]
    float* z_sh  = sh + Kc * Dd;             // [8][1024]
    float* e2_sh = z_sh + VQ_SAMPLES * H1;   // [Kc]

    const int tid  = threadIdx.x;
    const int warp = tid >> 5;
    const int lane = tid & 31;
    const size_t b0 = (size_t)blockIdx.x * VQ_SAMPLES;

#pragma unroll
    for (int i = 0; i < (Kc * Dd / 4) / 256; ++i)
        reinterpret_cast<float4*>(E_sh)[tid + i * 256] =
            reinterpret_cast<const float4*>(E)[tid + i * 256];
#pragma unroll
    for (int i = 0; i < (VQ_SAMPLES * H1 / 4) / 256; ++i)
        reinterpret_cast<float4*>(z_sh)[tid + i * 256] =
            reinterpret_cast<const float4*>(z_e + b0 * H1)[tid + i * 256];
    __syncthreads();

    if (tid < Kc) {
        float s = 0.f;
#pragma unroll 16
        for (int d = 0; d < Dd; ++d) {
            float v = E_sh[d * Kc + tid];
            s = __fadd_rn(s, __fmul_rn(v, v));
        }
        e2_sh[tid] = s;
    }
    __syncthreads();

    const int s = warp;
    const float* zrow = z_sh + s * H1;

    float s2 = 0.f;
    {
        const int n = lane & 7;
#pragma unroll 16
        for (int d = 0; d < Dd; ++d) {
            float v = zrow[d * 8 + n];
            s2 = __fadd_rn(s2, __fmul_rn(v, v));
        }
    }
    float z2v[Nn];
#pragma unroll
    for (int n = 0; n < Nn; ++n)
        z2v[n] = __shfl_sync(0xFFFFFFFFu, s2, n);

    float acc[Nn][4];
#pragma unroll
    for (int n = 0; n < Nn; ++n)
#pragma unroll
        for (int j = 0; j < 4; ++j) acc[n][j] = 0.f;

#pragma unroll 4
    for (int d = 0; d < Dd; ++d) {
        float4 ev = *reinterpret_cast<const float4*>(&E_sh[d * Kc + lane * 4]);
        float4 za = *reinterpret_cast<const float4*>(&zrow[d * 8]);
        float4 zb = *reinterpret_cast<const float4*>(&zrow[d * 8 + 4]);
        acc[0][0] = fmaf(za.x, ev.x, acc[0][0]); acc[0][1] = fmaf(za.x, ev.y, acc[0][1]);
        acc[0][2] = fmaf(za.x, ev.z, acc[0][2]); acc[0][3] = fmaf(za.x, ev.w, acc[0][3]);
        acc[1][0] = fmaf(za.y, ev.x, acc[1][0]); acc[1][1] = fmaf(za.y, ev.y, acc[1][1]);
        acc[1][2] = fmaf(za.y, ev.z, acc[1][2]); acc[1][3] = fmaf(za.y, ev.w, acc[1][3]);
        acc[2][0] = fmaf(za.z, ev.x, acc[2][0]); acc[2][1] = fmaf(za.z, ev.y, acc[2][1]);
        acc[2][2] = fmaf(za.z, ev.z, acc[2][2]); acc[2][3] = fmaf(za.z, ev.w, acc[2][3]);
        acc[3][0] = fmaf(za.w, ev.x, acc[3][0]); acc[3][1] = fmaf(za.w, ev.y, acc[3][1]);
        acc[3][2] = fmaf(za.w, ev.z, acc[3][2]); acc[3][3] = fmaf(za.w, ev.w, acc[3][3]);
        acc[4][0] = fmaf(zb.x, ev.x, acc[4][0]); acc[4][1] = fmaf(zb.x, ev.y, acc[4][1]);
        acc[4][2] = fmaf(zb.x, ev.z, acc[4][2]); acc[4][3] = fmaf(zb.x, ev.w, acc[4][3]);
        acc[5][0] = fmaf(zb.y, ev.x, acc[5][0]); acc[5][1] = fmaf(zb.y, ev.y, acc[5][1]);
        acc[5][2] = fmaf(zb.y, ev.z, acc[5][2]); acc[5][3] = fmaf(zb.y, ev.w, acc[5][3]);
        acc[6][0] = fmaf(zb.z, ev.x, acc[6][0]); acc[6][1] = fmaf(zb.z, ev.y, acc[6][1]);
        acc[6][2] = fmaf(zb.z, ev.z, acc[6][2]); acc[6][3] = fmaf(zb.z, ev.w, acc[6][3]);
        acc[7][0] = fmaf(zb.w, ev.x, acc[7][0]); acc[7][1] = fmaf(zb.w, ev.y, acc[7][1]);
        acc[7][2] = fmaf(zb.w, ev.z, acc[7][2]); acc[7][3] = fmaf(zb.w, ev.w, acc[7][3]);
    }

    const float4 e4 = *reinterpret_cast<const float4*>(&e2_sh[lane * 4]);

    int bi_arr[Nn];
#pragma unroll
    for (int n = 0; n < Nn; ++n) {
        const float z2n = z2v[n];
        float v0 = __fadd_rn(fmaf(-2.0f, acc[n][0], z2n), e4.x);
        float v1 = __fadd_rn(fmaf(-2.0f, acc[n][1], z2n), e4.y);
        float v2 = __fadd_rn(fmaf(-2.0f, acc[n][2], z2n), e4.z);
        float v3 = __fadd_rn(fmaf(-2.0f, acc[n][3], z2n), e4.w);

        float best = v0; int bi = lane * 4;
        if (v1 < best) { best = v1; bi = lane * 4 + 1; }
        if (v2 < best) { best = v2; bi = lane * 4 + 2; }
        if (v3 < best) { best = v3; bi = lane * 4 + 3; }
#pragma unroll
        for (int off = 16; off > 0; off >>= 1) {
            float ov = __shfl_xor_sync(0xFFFFFFFFu, best, off);
            int   oi = __shfl_xor_sync(0xFFFFFFFFu, bi,  off);
            if (ov < best || (ov == best && oi < bi)) { best = ov; bi = oi; }
        }
        bi_arr[n] = bi;
    }

    int bsel = bi_arr[0];
#pragma unroll
    for (int n = 1; n < Nn; ++n)
        if ((lane & 7) == n) bsel = bi_arr[n];

    if (lane < Nn)
        idx_out[(b0 + s) * Nn + lane] = bsel;

    float* erow = emb + (b0 + s) * H1;
#pragma unroll
    for (int t = 0; t < H1 / 32; ++t) {
        int i = t * 32 + lane;
        erow[i] = E_sh[(i >> 3) * Kc + bsel];
    }
}

// ---------------------------------------------------------------------------
// P[n,k,j] = sum_d E[d,k] * W3[d*8+n, j]
// ---------------------------------------------------------------------------
__global__ __launch_bounds__(128)
void build_P(const float* __restrict__ E, const float* __restrict__ W3,
             float* __restrict__ P)
{
    const int n = blockIdx.x >> 7;
    const int k = blockIdx.x & 127;
    const int j = threadIdx.x * 4;

    float4 acc = make_float4(0.f, 0.f, 0.f, 0.f);
#pragma unroll 8
    for (int d = 0; d < Dd; ++d) {
        const float e = __ldg(&E[d * Kc + k]);
        const float4 w = *reinterpret_cast<const float4*>(
            &W3[(size_t)(d * 8 + n) * H0 + j]);
        acc.x = fmaf(e, w.x, acc.x);
        acc.y = fmaf(e, w.y, acc.y);
        acc.z = fmaf(e, w.z, acc.z);
        acc.w = fmaf(e, w.w, acc.w);
    }
    *reinterpret_cast<float4*>(&P[((size_t)n * Kc + k) * H0 + j]) = acc;
}

// ---------------------------------------------------------------------------
// h3[b,j] = relu(b3[j] + sum_n P[n, idx[b,n], j])
// ---------------------------------------------------------------------------
__global__ __launch_bounds__(128, 8)
void decode_h3(const float* __restrict__ P, const int* __restrict__ idx,
               const float* __restrict__ b3, float* __restrict__ h3)
{
    __shared__ int sid[Nn];
    const int b = blockIdx.x;
    const int tid = threadIdx.x;
    if (tid < Nn) sid[tid] = idx[b * Nn + tid];
    __syncthreads();

    const int j = tid * 4;
    float4 acc = *reinterpret_cast<const float4*>(&b3[j]);
#pragma unroll
    for (int n = 0; n < Nn; ++n) {
        const float4 p = *reinterpret_cast<const float4*>(
            &P[((size_t)n * Kc + sid[n]) * H0 + j]);
        acc.x = __fadd_rn(acc.x, p.x);
        acc.y = __fadd_rn(acc.y, p.y);
        acc.z = __fadd_rn(acc.z, p.z);
        acc.w = __fadd_rn(acc.w, p.w);
    }
    acc.x = fmaxf(acc.x, 0.f);
    acc.y = fmaxf(acc.y, 0.f);
    acc.z = fmaxf(acc.z, 0.f);
    acc.w = fmaxf(acc.w, 0.f);
    *reinterpret_cast<float4*>(&h3[(size_t)b * H0 + j]) = acc;
}

// ---------------------------------------------------------------------------
extern "C" void kernel_launch(void* const* d_in, const int* in_sizes, int n_in,
                              void* d_out, int out_size)
{
    const float* x  = (const float*)d_in[0];
    const float* W1 = (const float*)d_in[1];
    const float* b1 = (const float*)d_in[2];
    const float* W2 = (const float*)d_in[3];
    const float* b2 = (const float*)d_in[4];
    const float* W3 = (const float*)d_in[5];
    const float* b3 = (const float*)d_in[6];
    const float* W4 = (const float*)d_in[7];
    const float* b4 = (const float*)d_in[8];
    const float* E  = (const float*)d_in[9];

    float* out   = (float*)d_out;
    float* recon = out;
    float* z_e   = out + (size_t)Bsz * IN_DIM;
    float* emb   = out + (size_t)Bsz * (IN_DIM + H1);

    void *p_h1, *p_h3, *p_P, *p_idx;
    cudaGetSymbolAddress(&p_h1,  g_h1);
    cudaGetSymbolAddress(&p_h3,  g_h3);
    cudaGetSymbolAddress(&p_P,   g_P);
    cudaGetSymbolAddress(&p_idx, g_idx);
    float* h1f = (float*)p_h1;
    float* h3f = (float*)p_h3;
    float* Pf  = (float*)p_P;
    int*   idxf = (int*)p_idx;

    static bool attr_set = false;
    if (!attr_set) {
        cudaFuncSetAttribute(vq_kernel,
                             cudaFuncAttributeMaxDynamicSharedMemorySize, VQ_SMEM);
        attr_set = true;
    }

    // P table (independent of batch chain; tiny)
    build_P<<<Nn * Kc, 128>>>(E, W3, Pf);

    // GEMM1: h1 = relu(x @ W1 + b1)
    {
        dim3 grid(H0 / 128, Bsz / 128);
        gemm_kernel<1><<<grid, 256>>>(x, W1, b1, h1f, Bsz, H0, IN_DIM);
    }
    // GEMM2: z_e = h1 @ W2 + b2
    {
        dim3 grid(H1 / 128, Bsz / 128);
        gemm_kernel<0><<<grid, 256>>>(h1f, W2, b2, z_e, Bsz, H1, H0);
    }
    // Fused VQ: z_e -> emb, idx
    vq_kernel<<<Bsz / VQ_SAMPLES, 256, VQ_SMEM>>>(z_e, E, emb, idxf);

    // h3 via P-table gather-sum (replaces GEMM3)
    decode_h3<<<Bsz, 128>>>(Pf, idxf, b3, h3f);

    // GEMM4 via tensor cores (3xTF32): recon = tanh(h3 @ W4 + b4)
    {
        dim3 grid((IN_DIM + 63) / 64, Bsz / 128);
        gemm4_tc<<<grid, 256>>>(h3f, W4, b4, recon);
    }
}

// round 13
// speedup vs baseline: 1.4669x; 1.1127x over previous
#include <cuda_runtime.h>
#include <cuda_bf16.h>
#include <math.h>

// ---------------------------------------------------------------------------
// VQ-VAE forward on GB300 (sm_103a). Round 13: TC GEMMs + exact argmin repair.
//   h1'  = relu(x @ W1 + b1)     [3xTF32 TC, approx ~1e-6]
//   z_e' = h1' @ W2 + b2         [3xTF32 TC] -> output region 2 (passes 1e-3)
//   VQ on z_e': argmin + top-2 gap; slots with gap < THETA flagged
//   repair: flagged slots recomputed with the EXACT scalar fp32 chain
//           (bitwise identical to the R10 zero-flip path), idx+emb fixed
//   h3   = relu(b3 + sum_n P[n,idx[b,n],:])   (P-table; GEMM3 eliminated)
//   recon= tanh(h3 @ W4 + b4)    [3xTF32 TC] -> output region 1
// Output layout: recon | z_e | emb  (fp32, concatenated)
// ---------------------------------------------------------------------------

#define Bsz    32768
#define IN_DIM 784
#define H0     512
#define H1     1024
#define Kc     128
#define Dd     128
#define Nn     8
#define THETA  4e-3f

// Scratch (__device__ globals; no allocation allowed)
__device__ __align__(16) float g_h1[Bsz * H0];            // 64 MB
__device__ __align__(16) float g_h3[Bsz * H0];            // 64 MB
__device__ __align__(16) float g_P[Nn * Kc * H0];         // 2 MB
__device__ int   g_idx[Bsz * Nn];                         // 1 MB
__device__ int   g_nrep;
__device__ int   g_replist[Bsz * Nn];                     // worst-case safe

// ---------------------------------------------------------------------------
// 3xTF32 tensor-core GEMM: C[M,N] = act(A[M,K] @ W[K,N] + bias)
// Block tile 128x64xBK16, 256 thr = 8 warps (4m x 2n), warp tile 32x32.
// M%128==0, K%16==0, N%4==0 (N edge guarded). ACT: 0=none,1=relu,2=tanh
// ---------------------------------------------------------------------------
__device__ __forceinline__ void split_tf32(float a, unsigned& hi, unsigned& lo) {
    unsigned h;
    asm("cvt.rna.tf32.f32 %0, %1;" : "=r"(h) : "f"(a));
    float l = a - __uint_as_float(h);
    unsigned lr;
    asm("cvt.rna.tf32.f32 %0, %1;" : "=r"(lr) : "f"(l));
    hi = h; lo = lr;
}

__device__ __forceinline__ void mma_tf32(float4& d, const unsigned* a, const unsigned* b) {
    asm("mma.sync.aligned.m16n8k8.row.col.f32.tf32.tf32.f32 "
        "{%0,%1,%2,%3}, {%4,%5,%6,%7}, {%8,%9}, {%0,%1,%2,%3};"
        : "+f"(d.x), "+f"(d.y), "+f"(d.z), "+f"(d.w)
        : "r"(a[0]), "r"(a[1]), "r"(a[2]), "r"(a[3]), "r"(b[0]), "r"(b[1]));
}

template <int ACT>
__global__ __launch_bounds__(256, 2)
void gemm_tc(const float* __restrict__ A, const float* __restrict__ W,
             const float* __restrict__ bias, float* __restrict__ C,
             int M, int N, int K)
{
    __shared__ float As[2][128][20];
    __shared__ float Bs[2][16][72];

    const int tid  = threadIdx.x;
    const int warp = tid >> 5;
    const int lane = tid & 31;
    const int gid  = lane >> 2;
    const int tig  = lane & 3;

    const int m0 = blockIdx.y * 128;
    const int n0 = blockIdx.x * 64;
    const int wm = (warp >> 1) * 32;
    const int wn = (warp & 1) * 32;

    const int a_row = tid >> 2;
    const int a_q   = (tid & 3) * 4;
    const int b_row = tid >> 4;
    const int b_q   = (tid & 15) * 4;
    const bool b_ok = (n0 + b_q < N);

    float4 acc[2][4];
#pragma unroll
    for (int mt = 0; mt < 2; ++mt)
#pragma unroll
        for (int nt = 0; nt < 4; ++nt)
            acc[mt][nt] = make_float4(0.f, 0.f, 0.f, 0.f);

    const int nsteps = K / 16;

    float4 av0 = *reinterpret_cast<const float4*>(&A[(size_t)(m0 + a_row) * K + a_q]);
    float4 av1 = *reinterpret_cast<const float4*>(&A[(size_t)(m0 + 64 + a_row) * K + a_q]);
    float4 bv  = make_float4(0.f, 0.f, 0.f, 0.f);
    if (b_ok)
        bv = *reinterpret_cast<const float4*>(&W[(size_t)b_row * N + n0 + b_q]);
    *reinterpret_cast<float4*>(&As[0][a_row][a_q])      = av0;
    *reinterpret_cast<float4*>(&As[0][64 + a_row][a_q]) = av1;
    *reinterpret_cast<float4*>(&Bs[0][b_row][b_q])      = bv;
    __syncthreads();

    for (int s = 0; s < nsteps; ++s) {
        const int cur = s & 1;
        const bool more = (s + 1 < nsteps);

        if (more) {
            const int k0 = (s + 1) * 16;
            av0 = *reinterpret_cast<const float4*>(&A[(size_t)(m0 + a_row) * K + k0 + a_q]);
            av1 = *reinterpret_cast<const float4*>(&A[(size_t)(m0 + 64 + a_row) * K + k0 + a_q]);
            if (b_ok)
                bv = *reinterpret_cast<const float4*>(&W[(size_t)(k0 + b_row) * N + n0 + b_q]);
        }

#pragma unroll
        for (int k8 = 0; k8 < 16; k8 += 8) {
            unsigned ahi[2][4], alo[2][4];
#pragma unroll
            for (int mt = 0; mt < 2; ++mt) {
                const int rb = wm + mt * 16;
                float af0 = As[cur][rb + gid][k8 + tig];
                float af1 = As[cur][rb + gid + 8][k8 + tig];
                float af2 = As[cur][rb + gid][k8 + tig + 4];
                float af3 = As[cur][rb + gid + 8][k8 + tig + 4];
                split_tf32(af0, ahi[mt][0], alo[mt][0]);
                split_tf32(af1, ahi[mt][1], alo[mt][1]);
                split_tf32(af2, ahi[mt][2], alo[mt][2]);
                split_tf32(af3, ahi[mt][3], alo[mt][3]);
            }
            unsigned bhi[4][2], blo[4][2];
#pragma unroll
            for (int nt = 0; nt < 4; ++nt) {
                const int cb = wn + nt * 8 + gid;
                float bf0 = Bs[cur][k8 + tig][cb];
                float bf1 = Bs[cur][k8 + tig + 4][cb];
                split_tf32(bf0, bhi[nt][0], blo[nt][0]);
                split_tf32(bf1, bhi[nt][1], blo[nt][1]);
            }
#pragma unroll
            for (int mt = 0; mt < 2; ++mt)
#pragma unroll
                for (int nt = 0; nt < 4; ++nt) {
                    mma_tf32(acc[mt][nt], alo[mt], bhi[nt]);
                    mma_tf32(acc[mt][nt], ahi[mt], blo[nt]);
                    mma_tf32(acc[mt][nt], ahi[mt], bhi[nt]);
                }
        }

        if (more) {
            const int nxt = cur ^ 1;
            *reinterpret_cast<float4*>(&As[nxt][a_row][a_q])      = av0;
            *reinterpret_cast<float4*>(&As[nxt][64 + a_row][a_q]) = av1;
            *reinterpret_cast<float4*>(&Bs[nxt][b_row][b_q])      = bv;
        }
        __syncthreads();
    }

#pragma unroll
    for (int mt = 0; mt < 2; ++mt) {
        const int r0 = m0 + wm + mt * 16 + gid;
        const int r1 = r0 + 8;
#pragma unroll
        for (int nt = 0; nt < 4; ++nt) {
            const int c0 = n0 + wn + nt * 8 + 2 * tig;
            const int c1 = c0 + 1;
            if (c0 < N) {
                const float bb = bias[c0];
                float u = __fadd_rn(acc[mt][nt].x, bb);
                float v = __fadd_rn(acc[mt][nt].z, bb);
                if (ACT == 1) { u = fmaxf(u, 0.f); v = fmaxf(v, 0.f); }
                if (ACT == 2) { u = tanhf(u); v = tanhf(v); }
                C[(size_t)r0 * N + c0] = u;
                C[(size_t)r1 * N + c0] = v;
            }
            if (c1 < N) {
                const float bb = bias[c1];
                float u = __fadd_rn(acc[mt][nt].y, bb);
                float v = __fadd_rn(acc[mt][nt].w, bb);
                if (ACT == 1) { u = fmaxf(u, 0.f); v = fmaxf(v, 0.f); }
                if (ACT == 2) { u = tanhf(u); v = tanhf(v); }
                C[(size_t)r0 * N + c1] = u;
                C[(size_t)r1 * N + c1] = v;
            }
        }
    }
}

// ---------------------------------------------------------------------------
__global__ void zero_nrep() { if (threadIdx.x == 0) g_nrep = 0; }

// ---------------------------------------------------------------------------
// Fused VQ with top-2 gap flagging. Dist arithmetic as in R10 (jnp-ordered).
// Slots with (second_best - best) < THETA are appended to g_replist.
// ---------------------------------------------------------------------------
#define VQ_SAMPLES 8
#define VQ_SMEM ((Kc * Dd + VQ_SAMPLES * H1 + Kc) * (int)sizeof(float))

__global__ __launch_bounds__(256, 2)
void vq_kernel(const float* __restrict__ z_e, const float* __restrict__ E,
               float* __restrict__ emb, int* __restrict__ idx_out)
{
    extern __shared__ float sh[];
    float* E_sh  = sh;
    float* z_sh  = sh + Kc * Dd;
    float* e2_sh = z_sh + VQ_SAMPLES * H1;

    const int tid  = threadIdx.x;
    const int warp = tid >> 5;
    const int lane = tid & 31;
    const size_t b0 = (size_t)blockIdx.x * VQ_SAMPLES;

#pragma unroll
    for (int i = 0; i < (Kc * Dd / 4) / 256; ++i)
        reinterpret_cast<float4*>(E_sh)[tid + i * 256] =
            reinterpret_cast<const float4*>(E)[tid + i * 256];
#pragma unroll
    for (int i = 0; i < (VQ_SAMPLES * H1 / 4) / 256; ++i)
        reinterpret_cast<float4*>(z_sh)[tid + i * 256] =
            reinterpret_cast<const float4*>(z_e + b0 * H1)[tid + i * 256];
    __syncthreads();

    if (tid < Kc) {
        float s = 0.f;
#pragma unroll 16
        for (int d = 0; d < Dd; ++d) {
            float v = E_sh[d * Kc + tid];
            s = __fadd_rn(s, __fmul_rn(v, v));
        }
        e2_sh[tid] = s;
    }
    __syncthreads();

    const int s = warp;
    const float* zrow = z_sh + s * H1;

    float s2 = 0.f;
    {
        const int n = lane & 7;
#pragma unroll 16
        for (int d = 0; d < Dd; ++d) {
            float v = zrow[d * 8 + n];
            s2 = __fadd_rn(s2, __fmul_rn(v, v));
        }
    }
    float z2v[Nn];
#pragma unroll
    for (int n = 0; n < Nn; ++n)
        z2v[n] = __shfl_sync(0xFFFFFFFFu, s2, n);

    float acc[Nn][4];
#pragma unroll
    for (int n = 0; n < Nn; ++n)
#pragma unroll
        for (int j = 0; j < 4; ++j) acc[n][j] = 0.f;

#pragma unroll 4
    for (int d = 0; d < Dd; ++d) {
        float4 ev = *reinterpret_cast<const float4*>(&E_sh[d * Kc + lane * 4]);
        float4 za = *reinterpret_cast<const float4*>(&zrow[d * 8]);
        float4 zb = *reinterpret_cast<const float4*>(&zrow[d * 8 + 4]);
        acc[0][0] = fmaf(za.x, ev.x, acc[0][0]); acc[0][1] = fmaf(za.x, ev.y, acc[0][1]);
        acc[0][2] = fmaf(za.x, ev.z, acc[0][2]); acc[0][3] = fmaf(za.x, ev.w, acc[0][3]);
        acc[1][0] = fmaf(za.y, ev.x, acc[1][0]); acc[1][1] = fmaf(za.y, ev.y, acc[1][1]);
        acc[1][2] = fmaf(za.y, ev.z, acc[1][2]); acc[1][3] = fmaf(za.y, ev.w, acc[1][3]);
        acc[2][0] = fmaf(za.z, ev.x, acc[2][0]); acc[2][1] = fmaf(za.z, ev.y, acc[2][1]);
        acc[2][2] = fmaf(za.z, ev.z, acc[2][2]); acc[2][3] = fmaf(za.z, ev.w, acc[2][3]);
        acc[3][0] = fmaf(za.w, ev.x, acc[3][0]); acc[3][1] = fmaf(za.w, ev.y, acc[3][1]);
        acc[3][2] = fmaf(za.w, ev.z, acc[3][2]); acc[3][3] = fmaf(za.w, ev.w, acc[3][3]);
        acc[4][0] = fmaf(zb.x, ev.x, acc[4][0]); acc[4][1] = fmaf(zb.x, ev.y, acc[4][1]);
        acc[4][2] = fmaf(zb.x, ev.z, acc[4][2]); acc[4][3] = fmaf(zb.x, ev.w, acc[4][3]);
        acc[5][0] = fmaf(zb.y, ev.x, acc[5][0]); acc[5][1] = fmaf(zb.y, ev.y, acc[5][1]);
        acc[5][2] = fmaf(zb.y, ev.z, acc[5][2]); acc[5][3] = fmaf(zb.y, ev.w, acc[5][3]);
        acc[6][0] = fmaf(zb.z, ev.x, acc[6][0]); acc[6][1] = fmaf(zb.z, ev.y, acc[6][1]);
        acc[6][2] = fmaf(zb.z, ev.z, acc[6][2]); acc[6][3] = fmaf(zb.z, ev.w, acc[6][3]);
        acc[7][0] = fmaf(zb.w, ev.x, acc[7][0]); acc[7][1] = fmaf(zb.w, ev.y, acc[7][1]);
        acc[7][2] = fmaf(zb.w, ev.z, acc[7][2]); acc[7][3] = fmaf(zb.w, ev.w, acc[7][3]);
    }

    const float4 e4 = *reinterpret_cast<const float4*>(&e2_sh[lane * 4]);

    int bi_arr[Nn];
#pragma unroll
    for (int n = 0; n < Nn; ++n) {
        const float z2n = z2v[n];
        float v[4];
        v[0] = __fadd_rn(fmaf(-2.0f, acc[n][0], z2n), e4.x);
        v[1] = __fadd_rn(fmaf(-2.0f, acc[n][1], z2n), e4.y);
        v[2] = __fadd_rn(fmaf(-2.0f, acc[n][2], z2n), e4.z);
        v[3] = __fadd_rn(fmaf(-2.0f, acc[n][3], z2n), e4.w);

        float best = v[0]; int bi = lane * 4;
        float sec  = 3.4e38f;
#pragma unroll
        for (int j = 1; j < 4; ++j) {
            if (v[j] < best) { sec = best; best = v[j]; bi = lane * 4 + j; }
            else             { sec = fminf(sec, v[j]); }
        }
#pragma unroll
        for (int off = 16; off > 0; off >>= 1) {
            float ov = __shfl_xor_sync(0xFFFFFFFFu, best, off);
            int   oi = __shfl_xor_sync(0xFFFFFFFFu, bi,  off);
            float os = __shfl_xor_sync(0xFFFFFFFFu, sec, off);
            if (ov < best || (ov == best && oi < bi)) {
                sec = fminf(best, os);
                best = ov; bi = oi;
            } else {
                sec = fminf(sec, fminf(ov, os));
            }
        }
        bi_arr[n] = bi;
        // flag near-ties (all lanes agree; lane n writes)
        if (lane == n && (sec - best) < THETA) {
            int pos = atomicAdd(&g_nrep, 1);
            g_replist[pos] = (int)(b0 + s) * Nn + n;
        }
    }

    int bsel = bi_arr[0];
#pragma unroll
    for (int n = 1; n < Nn; ++n)
        if ((lane & 7) == n) bsel = bi_arr[n];

    if (lane < Nn)
        idx_out[(b0 + s) * Nn + lane] = bsel;

    float* erow = emb + (b0 + s) * H1;
#pragma unroll
    for (int t = 0; t < H1 / 32; ++t) {
        int i = t * 32 + lane;
        erow[i] = E_sh[(i >> 3) * Kc + bsel];
    }
}

// ---------------------------------------------------------------------------
// Repair: recompute flagged slots with the EXACT scalar fp32 chain
// (identical ordering to the R10 passing kernel): h1 row k-ascending FFMA,
// z slot k-ascending FFMA, z2/e2 d-ascending mul/add, jnp-ordered dist,
// sequential first-min argmin. Overwrites idx + emb slot.
// ---------------------------------------------------------------------------
__global__ __launch_bounds__(256, 4)
void repair_kernel(const float* __restrict__ x,  const float* __restrict__ W1,
                   const float* __restrict__ b1, const float* __restrict__ W2,
                   const float* __restrict__ b2, const float* __restrict__ E,
                   float* __restrict__ emb, int* __restrict__ idx_out)
{
    __shared__ float xrow[IN_DIM];
    __shared__ float h1row[H0];
    __shared__ float zrow[Dd];
    __shared__ float dist[Kc];
    __shared__ float z2_sh;
    __shared__ int   kbest_sh;

    const int tid = threadIdx.x;
    const int nrep = g_nrep;

    for (int r = blockIdx.x; r < nrep; r += gridDim.x) {
        const int slot = g_replist[r];
        const int b = slot >> 3;
        const int n = slot & 7;

        // stage x row
        for (int i = tid; i < IN_DIM; i += 256)
            xrow[i] = x[(size_t)b * IN_DIM + i];
        __syncthreads();

        // exact h1 row: h1[j] = relu(fl(sum_k x[k]*W1[k,j]) + b1[j]), k-ascending FFMA
        for (int j = tid; j < H0; j += 256) {
            float a = 0.f;
            for (int k = 0; k < IN_DIM; ++k)
                a = fmaf(xrow[k], W1[(size_t)k * H0 + j], a);
            h1row[j] = fmaxf(__fadd_rn(a, b1[j]), 0.f);
        }
        __syncthreads();

        // exact z slot: z[d] = fl(sum_j h1[j]*W2[j, d*8+n]) + b2, k-ascending FFMA
        if (tid < Dd) {
            float a = 0.f;
            const int col = tid * 8 + n;
            for (int j = 0; j < H0; ++j)
                a = fmaf(h1row[j], W2[(size_t)j * H1 + col], a);
            zrow[tid] = __fadd_rn(a, b2[col]);
        }
        __syncthreads();

        // z2: d-ascending, separate mul/add
        if (tid == 0) {
            float s2 = 0.f;
            for (int d = 0; d < Dd; ++d)
                s2 = __fadd_rn(s2, __fmul_rn(zrow[d], zrow[d]));
            z2_sh = s2;
        }
        __syncthreads();

        // per-k: e2 (d-ascending mul/add), cross (d-ascending FFMA), jnp dist
        if (tid < Kc) {
            float e2 = 0.f, cr = 0.f;
            for (int d = 0; d < Dd; ++d) {
                const float ev = E[d * Kc + tid];
                e2 = __fadd_rn(e2, __fmul_rn(ev, ev));
                cr = fmaf(zrow[d], ev, cr);
            }
            dist[tid] = __fadd_rn(fmaf(-2.0f, cr, z2_sh), e2);
        }
        __syncthreads();

        // sequential first-min argmin (exact jnp tie rule)
        if (tid == 0) {
            float best = dist[0]; int bi = 0;
            for (int k = 1; k < Kc; ++k)
                if (dist[k] < best) { best = dist[k]; bi = k; }
            kbest_sh = bi;
            idx_out[slot] = bi;
        }
        __syncthreads();

        // overwrite emb slot
        if (tid < Dd)
            emb[(size_t)b * H1 + tid * 8 + n] = E[tid * Kc + kbest_sh];
        __syncthreads();
    }
}

// ---------------------------------------------------------------------------
// P[n,k,j] = sum_d E[d,k] * W3[d*8+n, j]
// ---------------------------------------------------------------------------
__global__ __launch_bounds__(128)
void build_P(const float* __restrict__ E, const float* __restrict__ W3,
             float* __restrict__ P)
{
    const int n = blockIdx.x >> 7;
    const int k = blockIdx.x & 127;
    const int j = threadIdx.x * 4;

    float4 acc = make_float4(0.f, 0.f, 0.f, 0.f);
#pragma unroll 8
    for (int d = 0; d < Dd; ++d) {
        const float e = __ldg(&E[d * Kc + k]);
        const float4 w = *reinterpret_cast<const float4*>(
            &W3[(size_t)(d * 8 + n) * H0 + j]);
        acc.x = fmaf(e, w.x, acc.x);
        acc.y = fmaf(e, w.y, acc.y);
        acc.z = fmaf(e, w.z, acc.z);
        acc.w = fmaf(e, w.w, acc.w);
    }
    *reinterpret_cast<float4*>(&P[((size_t)n * Kc + k) * H0 + j]) = acc;
}

// ---------------------------------------------------------------------------
// h3[b,j] = relu(b3[j] + sum_n P[n, idx[b,n], j])
// ---------------------------------------------------------------------------
__global__ __launch_bounds__(128, 8)
void decode_h3(const float* __restrict__ P, const int* __restrict__ idx,
               const float* __restrict__ b3, float* __restrict__ h3)
{
    __shared__ int sid[Nn];
    const int b = blockIdx.x;
    const int tid = threadIdx.x;
    if (tid < Nn) sid[tid] = idx[b * Nn + tid];
    __syncthreads();

    const int j = tid * 4;
    float4 acc = *reinterpret_cast<const float4*>(&b3[j]);
#pragma unroll
    for (int n = 0; n < Nn; ++n) {
        const float4 p = *reinterpret_cast<const float4*>(
            &P[((size_t)n * Kc + sid[n]) * H0 + j]);
        acc.x = __fadd_rn(acc.x, p.x);
        acc.y = __fadd_rn(acc.y, p.y);
        acc.z = __fadd_rn(acc.z, p.z);
        acc.w = __fadd_rn(acc.w, p.w);
    }
    acc.x = fmaxf(acc.x, 0.f);
    acc.y = fmaxf(acc.y, 0.f);
    acc.z = fmaxf(acc.z, 0.f);
    acc.w = fmaxf(acc.w, 0.f);
    *reinterpret_cast<float4*>(&h3[(size_t)b * H0 + j]) = acc;
}

// ---------------------------------------------------------------------------
extern "C" void kernel_launch(void* const* d_in, const int* in_sizes, int n_in,
                              void* d_out, int out_size)
{
    const float* x  = (const float*)d_in[0];
    const float* W1 = (const float*)d_in[1];
    const float* b1 = (const float*)d_in[2];
    const float* W2 = (const float*)d_in[3];
    const float* b2 = (const float*)d_in[4];
    const float* W3 = (const float*)d_in[5];
    const float* b3 = (const float*)d_in[6];
    const float* W4 = (const float*)d_in[7];
    const float* b4 = (const float*)d_in[8];
    const float* E  = (const float*)d_in[9];

    float* out   = (float*)d_out;
    float* recon = out;
    float* z_e   = out + (size_t)Bsz * IN_DIM;
    float* emb   = out + (size_t)Bsz * (IN_DIM + H1);

    void *p_h1, *p_h3, *p_P, *p_idx;
    cudaGetSymbolAddress(&p_h1,  g_h1);
    cudaGetSymbolAddress(&p_h3,  g_h3);
    cudaGetSymbolAddress(&p_P,   g_P);
    cudaGetSymbolAddress(&p_idx, g_idx);
    float* h1f = (float*)p_h1;
    float* h3f = (float*)p_h3;
    float* Pf  = (float*)p_P;
    int*   idxf = (int*)p_idx;

    static bool attr_set = false;
    if (!attr_set) {
        cudaFuncSetAttribute(vq_kernel,
                             cudaFuncAttributeMaxDynamicSharedMemorySize, VQ_SMEM);
        attr_set = true;
    }

    zero_nrep<<<1, 32>>>();
    build_P<<<Nn * Kc, 128>>>(E, W3, Pf);

    // GEMM1 (TC 3xTF32): h1' = relu(x @ W1 + b1)
    {
        dim3 grid(H0 / 64, Bsz / 128);
        gemm_tc<1><<<grid, 256>>>(x, W1, b1, h1f, Bsz, H0, IN_DIM);
    }
    // GEMM2 (TC 3xTF32): z_e' = h1' @ W2 + b2
    {
        dim3 grid(H1 / 64, Bsz / 128);
        gemm_tc<0><<<grid, 256>>>(h1f, W2, b2, z_e, Bsz, H1, H0);
    }
    // Fused VQ with gap flagging
    vq_kernel<<<Bsz / VQ_SAMPLES, 256, VQ_SMEM>>>(z_e, E, emb, idxf);

    // Exact repair of near-tie slots
    repair_kernel<<<1024, 256>>>(x, W1, b1, W2, b2, E, emb, idxf);

    // h3 via P-table gather-sum
    decode_h3<<<Bsz, 128>>>(Pf, idxf, b3, h3f);

    // GEMM4 (TC 3xTF32): recon = tanh(h3 @ W4 + b4)
    {
        dim3 grid((IN_DIM + 63) / 64, Bsz / 128);
        gemm_tc<2><<<grid, 256>>>(h3f, W4, b4, recon, Bsz, IN_DIM, H0);
    }
}